// round 1
// baseline (speedup 1.0000x reference)
#include <cuda_runtime.h>
#include <cstdint>

// GraphConvolution: out = segment_sum(w * (x@W)[src], dst) + bias
// N=100000 nodes, E=1.6M edges, D_IN=D_OUT=128.
//
// Phase 1: support = x @ W          (fp32 register-blocked GEMM -> g_support)
// Phase 2: out[n][:] = bias[:]      (init, out is poisoned by harness)
// Phase 3: out[dst] += w * support[src]   (1 warp/edge, red.global.add.v4.f32)

#define D_DIM 128
#define BM 64
#define BN 64
#define XS_STRIDE 129   // 128 + 1 pad: breaks bank correlation for per-k scalar reads
#define MAX_NODES 100000

__device__ float g_support[(size_t)MAX_NODES * D_DIM];

// ---------------------------------------------------------------------------
// GEMM: support[m][n] = sum_k x[m][k] * W[k][n]
// Block: 256 threads as (tx 0..15, ty 0..15). Tile: BM=64 rows x BN=64 cols.
// Each thread: 4x4 register accumulator. x tile staged in smem; W (64KB total,
// reused by every block) streamed via read-only LDG -> L1-resident.
// ---------------------------------------------------------------------------
__global__ __launch_bounds__(256) void gemm_kernel(
    const float* __restrict__ x, const float* __restrict__ W, int N)
{
    __shared__ float xs[BM * XS_STRIDE];   // 33 KB

    const int tid = threadIdx.x;
    const int tx  = tid & 15;
    const int ty  = tid >> 4;
    const int m_base = blockIdx.x * BM;
    const int n_base = blockIdx.y * BN;

    // Stage x tile [BM][128] into smem (zero-fill past N).
    #pragma unroll
    for (int it = 0; it < 8; ++it) {
        int idx = tid + it * 256;          // 2048 float4 = 64*128 floats
        int m   = idx >> 5;                // row 0..63
        int k4  = (idx & 31) * 4;          // col 0..124 step 4
        int gm  = m_base + m;
        float4 v = make_float4(0.f, 0.f, 0.f, 0.f);
        if (gm < N) v = *(const float4*)(x + (size_t)gm * D_DIM + k4);
        float* p = xs + m * XS_STRIDE + k4;
        p[0] = v.x; p[1] = v.y; p[2] = v.z; p[3] = v.w;
    }
    __syncthreads();

    float acc[4][4];
    #pragma unroll
    for (int i = 0; i < 4; ++i)
        #pragma unroll
        for (int j = 0; j < 4; ++j) acc[i][j] = 0.f;

    const float* xr0 = xs + (ty * 4 + 0) * XS_STRIDE;
    const float* xr1 = xs + (ty * 4 + 1) * XS_STRIDE;
    const float* xr2 = xs + (ty * 4 + 2) * XS_STRIDE;
    const float* xr3 = xs + (ty * 4 + 3) * XS_STRIDE;
    const float* wp  = W + n_base + tx * 4;

    #pragma unroll 16
    for (int k = 0; k < D_DIM; ++k) {
        float4 wv = __ldg((const float4*)(wp + (size_t)k * D_DIM));
        float x0 = xr0[k], x1 = xr1[k], x2 = xr2[k], x3 = xr3[k];
        acc[0][0] += x0 * wv.x; acc[0][1] += x0 * wv.y;
        acc[0][2] += x0 * wv.z; acc[0][3] += x0 * wv.w;
        acc[1][0] += x1 * wv.x; acc[1][1] += x1 * wv.y;
        acc[1][2] += x1 * wv.z; acc[1][3] += x1 * wv.w;
        acc[2][0] += x2 * wv.x; acc[2][1] += x2 * wv.y;
        acc[2][2] += x2 * wv.z; acc[2][3] += x2 * wv.w;
        acc[3][0] += x3 * wv.x; acc[3][1] += x3 * wv.y;
        acc[3][2] += x3 * wv.z; acc[3][3] += x3 * wv.w;
    }

    #pragma unroll
    for (int i = 0; i < 4; ++i) {
        int gm = m_base + ty * 4 + i;
        if (gm < N) {
            float4 r = make_float4(acc[i][0], acc[i][1], acc[i][2], acc[i][3]);
            *(float4*)(g_support + (size_t)gm * D_DIM + n_base + tx * 4) = r;
        }
    }
}

// ---------------------------------------------------------------------------
// Init: out[n][d] = bias[d]  (float4 broadcast)
// ---------------------------------------------------------------------------
__global__ void init_out_kernel(float* __restrict__ out,
                                const float* __restrict__ bias, int n4_total)
{
    int i = blockIdx.x * blockDim.x + threadIdx.x;
    if (i < n4_total) {
        ((float4*)out)[i] = ((const float4*)bias)[i & 31];  // 128 floats = 32 float4
    }
}

// ---------------------------------------------------------------------------
// Scatter: one warp per edge. Lane l handles floats [4l, 4l+4) of the row.
// Gather support[src] (coalesced 512B/warp, L2-resident) and reduce into
// out[dst] with vectorized no-return global reduction (sm_90+).
// ---------------------------------------------------------------------------
__global__ __launch_bounds__(256) void scatter_kernel(
    const int*   __restrict__ esrc,
    const int*   __restrict__ edst,
    const float* __restrict__ ew,
    float*       __restrict__ out, int E)
{
    int warp = (blockIdx.x * blockDim.x + threadIdx.x) >> 5;
    int lane = threadIdx.x & 31;
    if (warp >= E) return;

    int   s  = __ldg(esrc + warp);
    int   d  = __ldg(edst + warp);
    float wt = __ldg(ew   + warp);

    float4 v = *(const float4*)(g_support + (size_t)s * D_DIM + lane * 4);
    float4 r;
    r.x = v.x * wt; r.y = v.y * wt; r.z = v.z * wt; r.w = v.w * wt;

    float* p = out + (size_t)d * D_DIM + lane * 4;
    asm volatile("red.global.add.v4.f32 [%0], {%1, %2, %3, %4};"
                 :: "l"(p), "f"(r.x), "f"(r.y), "f"(r.z), "f"(r.w)
                 : "memory");
}

// ---------------------------------------------------------------------------
extern "C" void kernel_launch(void* const* d_in, const int* in_sizes, int n_in,
                              void* d_out, int out_size)
{
    const float* x    = (const float*)d_in[0];
    const int*   esrc = (const int*)  d_in[1];
    const int*   edst = (const int*)  d_in[2];
    const float* ew   = (const float*)d_in[3];
    const float* W    = (const float*)d_in[4];
    const float* bias = (const float*)d_in[5];
    float*       out  = (float*)d_out;

    const int N = in_sizes[0] / D_DIM;   // 100000
    const int E = in_sizes[1];           // 1600000

    // Phase 1: support = x @ W
    dim3 ggrid((N + BM - 1) / BM, D_DIM / BN);
    gemm_kernel<<<ggrid, 256>>>(x, W, N);

    // Phase 2: out = bias (broadcast)
    int n4_total = N * (D_DIM / 4);
    init_out_kernel<<<(n4_total + 255) / 256, 256>>>(out, bias, n4_total);

    // Phase 3: out[dst] += w * support[src]
    int warps_per_block = 256 / 32;
    int nblocks = (E + warps_per_block - 1) / warps_per_block;
    scatter_kernel<<<nblocks, 256>>>(esrc, edst, ew, out, E);
}

// round 7
// speedup vs baseline: 1.0372x; 1.0372x over previous
#include <cuda_runtime.h>
#include <cstdint>

// GraphConvolution: out = segment_sum(w * (x@W)[src], dst) + bias
// N=100000, E=1600000, D=128.
//
// Phase 1: support = x @ W   (FFMA2 fma.rn.f32x2 GEMM, static smem, k-chunked)
// Phase 2: build CSR by dst  (zero/hist/scan/reorder -> packed (src,w))
// Phase 3: pull-gather       (1 warp/dst, register acc, bias folded, no atomics)

#define D_DIM 128
#define BM 64
#define BN 128
#define KC 32                    // k-chunk size
#define NCHUNK (D_DIM / KC)      // 4
#define XT_STRIDE 66             // xsT row stride (even -> LDS.64 aligned)
#define WD_STRIDE 258            // wsd row stride (2*128 + 2, even)
#define MAX_NODES 100000
#define MAX_EDGES 1600000
#define SCAN_CHUNK 2048          // 256 threads * 8 elems
#define MAX_SCAN_BLOCKS 64       // ceil(100000/2048)=49

__device__ float g_support[(size_t)MAX_NODES * D_DIM];
__device__ int   g_cnt[MAX_NODES];          // histogram, then reused as cursor
__device__ int   g_start[MAX_NODES + 1];    // CSR row offsets
__device__ int   g_bsums[MAX_SCAN_BLOCKS];
__device__ int2  g_edges[MAX_EDGES];        // packed (src, weight-bits) by dst

// ---------------------------------------------------------------------------
// GEMM: support[m][n] = sum_k x[m][k] * W[k][n]
// 256 threads (tx 0..15, ty 0..15). Tile BM=64 x BN=128; 4 rows x 8 cols per
// thread as 2 row-pairs x 8, accumulated with fma.rn.f32x2.
//  - xsT[k][m]  : x transposed; LDS.64 at [k][4ty] -> (x_r, x_r+1) pair.
//  - wsd[k][2j] : W duplicated; LDS.64 at [k][2j]  -> (w_j, w_j) pair.
// Per k per thread: 2 + 8 LDS.64, 16 FFMA2. K in 4 chunks of 32 to keep
// static smem at 41.5 KB (no cudaFuncSetAttribute, no static guards).
// ---------------------------------------------------------------------------
__device__ __forceinline__ void ffma2(unsigned long long& acc,
                                      unsigned long long a,
                                      unsigned long long b)
{
    asm("fma.rn.f32x2 %0, %1, %2, %0;" : "+l"(acc) : "l"(a), "l"(b));
}

__global__ __launch_bounds__(256) void gemm_kernel(
    const float* __restrict__ x, const float* __restrict__ W, int N)
{
    __shared__ __align__(16) float xsT[KC * XT_STRIDE];   // 8448 B
    __shared__ __align__(16) float wsd[KC * WD_STRIDE];   // 33024 B

    const int tid = threadIdx.x;
    const int tx  = tid & 15;
    const int ty  = tid >> 4;
    const int m_base = blockIdx.x * BM;

    unsigned long long acc2[2][8];
    #pragma unroll
    for (int ip = 0; ip < 2; ++ip)
        #pragma unroll
        for (int jj = 0; jj < 8; ++jj) acc2[ip][jj] = 0ull;

    for (int c = 0; c < NCHUNK; ++c) {
        if (c) __syncthreads();   // previous chunk's compute done before restage

        // Stage x chunk transposed: 64 m x 32 k. idx -> (m = idx&63,
        // k4 = (idx>>6)*4). Warp: m consecutive -> conflict-free STS.32.
        #pragma unroll
        for (int it = 0; it < 2; ++it) {
            int idx = it * 256 + tid;            // 0..511
            int m   = idx & 63;
            int k4  = (idx >> 6) * 4;            // 0,4,...,28
            int gm  = m_base + m;
            float4 v = make_float4(0.f, 0.f, 0.f, 0.f);
            if (gm < N)
                v = *(const float4*)(x + (size_t)gm * D_DIM + c * KC + k4);
            xsT[(k4 + 0) * XT_STRIDE + m] = v.x;
            xsT[(k4 + 1) * XT_STRIDE + m] = v.y;
            xsT[(k4 + 2) * XT_STRIDE + m] = v.z;
            xsT[(k4 + 3) * XT_STRIDE + m] = v.w;
        }

        // Stage W chunk duplicated: 32 k x 128 j; wsd[k][2j]=[2j+1]=W[ck][j].
        // Warp reads 32 consecutive j (coalesced 128B).
        #pragma unroll
        for (int it = 0; it < 16; ++it) {
            int idx = it * 256 + tid;            // 0..4095
            int k   = idx >> 7;                  // 0..31
            int j   = idx & 127;                 // 0..127
            unsigned int b = __float_as_uint(
                __ldg(W + (size_t)(c * KC + k) * D_DIM + j));
            unsigned long long d = ((unsigned long long)b << 32) | b;
            *(unsigned long long*)(wsd + (size_t)k * WD_STRIDE + 2 * j) = d;
        }
        __syncthreads();

        const float* xr = xsT + 4 * ty;
        const float* wr = wsd + 2 * tx;

        #pragma unroll 4
        for (int k = 0; k < KC; ++k) {
            unsigned long long x20 =
                *(const unsigned long long*)(xr + k * XT_STRIDE);
            unsigned long long x21 =
                *(const unsigned long long*)(xr + k * XT_STRIDE + 2);
            #pragma unroll
            for (int jj = 0; jj < 8; ++jj) {
                unsigned long long w =
                    *(const unsigned long long*)(wr + k * WD_STRIDE + 32 * jj);
                ffma2(acc2[0][jj], x20, w);
                ffma2(acc2[1][jj], x21, w);
            }
        }
    }

    // Epilogue: acc2[ip][jj] = (row 4ty+2ip -> lo, row 4ty+2ip+1 -> hi),
    // col = tx + 16*jj.
    #pragma unroll
    for (int ip = 0; ip < 2; ++ip) {
        int r0 = m_base + 4 * ty + 2 * ip;
        #pragma unroll
        for (int jj = 0; jj < 8; ++jj) {
            int col = tx + 16 * jj;
            float lo = __uint_as_float((unsigned int)(acc2[ip][jj]));
            float hi = __uint_as_float((unsigned int)(acc2[ip][jj] >> 32));
            if (r0 < N)     g_support[(size_t)r0 * D_DIM + col]       = lo;
            if (r0 + 1 < N) g_support[(size_t)(r0 + 1) * D_DIM + col] = hi;
        }
    }
}

// ---------------------------------------------------------------------------
// CSR build
// ---------------------------------------------------------------------------
__global__ void zero_cnt_kernel(int N)
{
    int i = blockIdx.x * blockDim.x + threadIdx.x;
    if (i < N) g_cnt[i] = 0;
}

__global__ void hist_kernel(const int* __restrict__ edst, int E)
{
    int e = blockIdx.x * blockDim.x + threadIdx.x;
    if (e < E) atomicAdd(&g_cnt[edst[e]], 1);
}

// pass 1: per-block totals of g_cnt chunks
__global__ __launch_bounds__(256) void scan1_kernel(int N)
{
    __shared__ int sT[256];
    int t = threadIdx.x;
    int base = blockIdx.x * SCAN_CHUNK + t * 8;
    int tot = 0;
    #pragma unroll
    for (int i = 0; i < 8; ++i) {
        int idx = base + i;
        tot += (idx < N) ? g_cnt[idx] : 0;
    }
    sT[t] = tot; __syncthreads();
    #pragma unroll
    for (int off = 128; off > 0; off >>= 1) {
        if (t < off) sT[t] += sT[t + off];
        __syncthreads();
    }
    if (t == 0) g_bsums[blockIdx.x] = sT[0];
}

// pass 2: serial exclusive scan of block sums (NB <= 64)
__global__ void scan2_kernel(int NB, int N)
{
    if (threadIdx.x == 0) {
        int acc = 0;
        for (int i = 0; i < NB; ++i) {
            int v = g_bsums[i];
            g_bsums[i] = acc;
            acc += v;
        }
        g_start[N] = acc;   // == E
    }
}

// pass 3: full exclusive scan -> g_start; reset g_cnt to 0 (cursor reuse)
__global__ __launch_bounds__(256) void scan3_kernel(int N)
{
    __shared__ int sT[256];
    int t = threadIdx.x;
    int base = blockIdx.x * SCAN_CHUNK + t * 8;

    int c[8];
    int tot = 0;
    #pragma unroll
    for (int i = 0; i < 8; ++i) {
        int idx = base + i;
        c[i] = (idx < N) ? g_cnt[idx] : 0;
        tot += c[i];
    }
    sT[t] = tot; __syncthreads();
    // inclusive Hillis-Steele
    #pragma unroll
    for (int off = 1; off < 256; off <<= 1) {
        int v = (t >= off) ? sT[t - off] : 0;
        __syncthreads();
        sT[t] += v;
        __syncthreads();
    }
    int run = g_bsums[blockIdx.x] + sT[t] - tot;   // exclusive thread base
    #pragma unroll
    for (int i = 0; i < 8; ++i) {
        int idx = base + i;
        if (idx < N) {
            g_start[idx] = run;
            g_cnt[idx]   = 0;
        }
        run += c[i];
    }
}

// reorder edges into dst-grouped packed (src, weight-bits)
__global__ void reorder_kernel(const int* __restrict__ esrc,
                               const int* __restrict__ edst,
                               const float* __restrict__ ew, int E)
{
    int e = blockIdx.x * blockDim.x + threadIdx.x;
    if (e < E) {
        int d = edst[e];
        int p = g_start[d] + atomicAdd(&g_cnt[d], 1);
        g_edges[p] = make_int2(esrc[e], __float_as_int(ew[e]));
    }
}

// ---------------------------------------------------------------------------
// Pull-gather: one warp per dst node. lane l covers floats [4l, 4l+4).
// acc starts at bias; single float4 store per lane. No atomics.
// 4x edge unroll: 4 independent support loads in flight (MLP vs ~234cy L2).
// ---------------------------------------------------------------------------
__global__ __launch_bounds__(512) void gather_kernel(
    const float* __restrict__ bias, float* __restrict__ out, int N)
{
    int n    = (blockIdx.x * blockDim.x + threadIdx.x) >> 5;
    int lane = threadIdx.x & 31;
    if (n >= N) return;

    int j   = g_start[n];
    int end = g_start[n + 1];

    float4 a0 = __ldg((const float4*)(bias + lane * 4));
    float4 a1 = make_float4(0.f, 0.f, 0.f, 0.f);
    float4 a2 = make_float4(0.f, 0.f, 0.f, 0.f);
    float4 a3 = make_float4(0.f, 0.f, 0.f, 0.f);

    const size_t loff = (size_t)lane * 4;

    for (; j + 4 <= end; j += 4) {
        int2 e0 = __ldg(&g_edges[j]);
        int2 e1 = __ldg(&g_edges[j + 1]);
        int2 e2 = __ldg(&g_edges[j + 2]);
        int2 e3 = __ldg(&g_edges[j + 3]);
        float4 v0 = *(const float4*)(g_support + (size_t)e0.x * D_DIM + loff);
        float4 v1 = *(const float4*)(g_support + (size_t)e1.x * D_DIM + loff);
        float4 v2 = *(const float4*)(g_support + (size_t)e2.x * D_DIM + loff);
        float4 v3 = *(const float4*)(g_support + (size_t)e3.x * D_DIM + loff);
        float w0 = __int_as_float(e0.y), w1 = __int_as_float(e1.y);
        float w2 = __int_as_float(e2.y), w3 = __int_as_float(e3.y);
        a0.x += w0 * v0.x; a0.y += w0 * v0.y; a0.z += w0 * v0.z; a0.w += w0 * v0.w;
        a1.x += w1 * v1.x; a1.y += w1 * v1.y; a1.z += w1 * v1.z; a1.w += w1 * v1.w;
        a2.x += w2 * v2.x; a2.y += w2 * v2.y; a2.z += w2 * v2.z; a2.w += w2 * v2.w;
        a3.x += w3 * v3.x; a3.y += w3 * v3.y; a3.z += w3 * v3.z; a3.w += w3 * v3.w;
    }
    if (j + 2 <= end) {
        int2 e0 = __ldg(&g_edges[j]);
        int2 e1 = __ldg(&g_edges[j + 1]);
        float4 v0 = *(const float4*)(g_support + (size_t)e0.x * D_DIM + loff);
        float4 v1 = *(const float4*)(g_support + (size_t)e1.x * D_DIM + loff);
        float w0 = __int_as_float(e0.y), w1 = __int_as_float(e1.y);
        a0.x += w0 * v0.x; a0.y += w0 * v0.y; a0.z += w0 * v0.z; a0.w += w0 * v0.w;
        a1.x += w1 * v1.x; a1.y += w1 * v1.y; a1.z += w1 * v1.z; a1.w += w1 * v1.w;
        j += 2;
    }
    if (j < end) {
        int2 e0 = __ldg(&g_edges[j]);
        float4 v0 = *(const float4*)(g_support + (size_t)e0.x * D_DIM + loff);
        float w0 = __int_as_float(e0.y);
        a0.x += w0 * v0.x; a0.y += w0 * v0.y; a0.z += w0 * v0.z; a0.w += w0 * v0.w;
    }

    a0.x += a1.x + a2.x + a3.x;
    a0.y += a1.y + a2.y + a3.y;
    a0.z += a1.z + a2.z + a3.z;
    a0.w += a1.w + a2.w + a3.w;

    *(float4*)(out + (size_t)n * D_DIM + loff) = a0;
}

// ---------------------------------------------------------------------------
extern "C" void kernel_launch(void* const* d_in, const int* in_sizes, int n_in,
                              void* d_out, int out_size)
{
    const float* x    = (const float*)d_in[0];
    const int*   esrc = (const int*)  d_in[1];
    const int*   edst = (const int*)  d_in[2];
    const float* ew   = (const float*)d_in[3];
    const float* W    = (const float*)d_in[4];
    const float* bias = (const float*)d_in[5];
    float*       out  = (float*)d_out;

    const int N = in_sizes[0] / D_DIM;   // 100000
    const int E = in_sizes[1];           // 1600000
    const int NB = (N + SCAN_CHUNK - 1) / SCAN_CHUNK;   // 49

    // Phase 1: support = x @ W  (static smem, single N-block column)
    gemm_kernel<<<(N + BM - 1) / BM, 256>>>(x, W, N);

    // Phase 2: CSR build by dst
    zero_cnt_kernel<<<(N + 255) / 256, 256>>>(N);
    hist_kernel<<<(E + 255) / 256, 256>>>(edst, E);
    scan1_kernel<<<NB, 256>>>(N);
    scan2_kernel<<<1, 32>>>(NB, N);
    scan3_kernel<<<NB, 256>>>(N);
    reorder_kernel<<<(E + 255) / 256, 256>>>(esrc, edst, ew, E);

    // Phase 3: pull-gather with bias (16 warps/block)
    int nblocks = (N * 32 + 511) / 512;
    gather_kernel<<<nblocks, 512>>>(bias, out, N);
}

// round 9
// speedup vs baseline: 1.2998x; 1.2531x over previous
#include <cuda_runtime.h>
#include <cstdint>

// GraphConvolution: out = segment_sum(w * (x@W)[src], dst) + bias
// N=100000, E=1600000, D=128.
//
// Phase 1: support = x @ W   (FFMA2 GEMM: x-pairs from transposed smem,
//                             W via L1 LDG.128, pairs packed in registers)
// Phase 2: build CSR by dst  (zero/hist/scan/reorder -> packed (src,w))
// Phase 3: pull-gather       (1 warp/dst, register acc, bias folded, no atomics)

#define D_DIM 128
#define BM 64
#define BN 64
#define XT_STRIDE 66             // xsT row stride (even -> LDS.64 aligned)
#define MAX_NODES 100000
#define MAX_EDGES 1600000
#define SCAN_CHUNK 2048          // 256 threads * 8 elems
#define MAX_SCAN_BLOCKS 64       // ceil(100000/2048)=49

__device__ float g_support[(size_t)MAX_NODES * D_DIM];
__device__ int   g_cnt[MAX_NODES];          // histogram, then reused as cursor
__device__ int   g_start[MAX_NODES + 1];    // CSR row offsets
__device__ int   g_bsums[MAX_SCAN_BLOCKS];
__device__ int2  g_edges[MAX_EDGES];        // packed (src, weight-bits) by dst

// ---------------------------------------------------------------------------
// GEMM: support[m][n] = sum_k x[m][k] * W[k][n]
// 256 threads (tx 0..15, ty 0..15). Tile BM=64 x BN=64; thread computes
// 4 rows x 4 cols as 2 row-pairs x 4 via fma.rn.f32x2.
//  - xsT[k][m]: x transposed in smem; LDS.64 at [k][4ty] -> (x_r, x_r+1).
//  - W row k, cols tx*4..tx*4+3 via __ldg float4 (L1-resident, 64KB total);
//    (w,w) pairs packed in registers (mov.b64) -> no duplicated smem traffic.
// Per thread per k: 8 FFMA2 + 2 LDS.64 + 1 LDG.128 + 4 packs.
// Per CTA per k: LDS crossbar 32 cyc == fma pipe 32 cyc (balanced, 2x scalar).
// ---------------------------------------------------------------------------
__device__ __forceinline__ void ffma2(unsigned long long& acc,
                                      unsigned long long a,
                                      unsigned long long b)
{
    asm("fma.rn.f32x2 %0, %1, %2, %0;" : "+l"(acc) : "l"(a), "l"(b));
}

__device__ __forceinline__ unsigned long long pack_dup(float w)
{
    unsigned long long d;
    unsigned int b = __float_as_uint(w);
    asm("mov.b64 %0, {%1, %1};" : "=l"(d) : "r"(b));
    return d;
}

__global__ __launch_bounds__(256) void gemm_kernel(
    const float* __restrict__ x, const float* __restrict__ W, int N)
{
    __shared__ __align__(16) float xsT[D_DIM * XT_STRIDE];   // 33792 B

    const int tid = threadIdx.x;
    const int tx  = tid & 15;
    const int ty  = tid >> 4;
    const int m_base = blockIdx.x * BM;
    const int n_base = blockIdx.y * BN;

    // Stage x tile transposed: 64 m x 128 k. idx -> (m = idx&63,
    // k4 = (idx>>6)*4). Warp: m lane-consecutive -> conflict-free STS.32.
    #pragma unroll
    for (int it = 0; it < 8; ++it) {
        int idx = it * 256 + tid;            // 0..2047
        int m   = idx & 63;
        int k4  = (idx >> 6) * 4;            // 0..124
        int gm  = m_base + m;
        float4 v = make_float4(0.f, 0.f, 0.f, 0.f);
        if (gm < N) v = *(const float4*)(x + (size_t)gm * D_DIM + k4);
        xsT[(k4 + 0) * XT_STRIDE + m] = v.x;
        xsT[(k4 + 1) * XT_STRIDE + m] = v.y;
        xsT[(k4 + 2) * XT_STRIDE + m] = v.z;
        xsT[(k4 + 3) * XT_STRIDE + m] = v.w;
    }
    __syncthreads();

    unsigned long long acc2[2][4];
    #pragma unroll
    for (int ip = 0; ip < 2; ++ip)
        #pragma unroll
        for (int jj = 0; jj < 4; ++jj) acc2[ip][jj] = 0ull;

    const float* xr = xsT + 4 * ty;
    const float* wp = W + n_base + tx * 4;

    #pragma unroll 8
    for (int k = 0; k < D_DIM; ++k) {
        unsigned long long x20 = *(const unsigned long long*)(xr + k * XT_STRIDE);
        unsigned long long x21 = *(const unsigned long long*)(xr + k * XT_STRIDE + 2);
        float4 wv = __ldg((const float4*)(wp + (size_t)k * D_DIM));
        unsigned long long w0 = pack_dup(wv.x);
        unsigned long long w1 = pack_dup(wv.y);
        unsigned long long w2 = pack_dup(wv.z);
        unsigned long long w3 = pack_dup(wv.w);
        ffma2(acc2[0][0], x20, w0); ffma2(acc2[1][0], x21, w0);
        ffma2(acc2[0][1], x20, w1); ffma2(acc2[1][1], x21, w1);
        ffma2(acc2[0][2], x20, w2); ffma2(acc2[1][2], x21, w2);
        ffma2(acc2[0][3], x20, w3); ffma2(acc2[1][3], x21, w3);
    }

    // Epilogue: acc2[ip][jj] covers rows (4ty+2ip [lo], 4ty+2ip+1 [hi]),
    // col n_base + tx*4 + jj. Regroup lo/hi into float4 row stores.
    #pragma unroll
    for (int ip = 0; ip < 2; ++ip) {
        int r0 = m_base + 4 * ty + 2 * ip;
        float4 lo4, hi4;
        lo4.x = __uint_as_float((unsigned int)(acc2[ip][0]));
        lo4.y = __uint_as_float((unsigned int)(acc2[ip][1]));
        lo4.z = __uint_as_float((unsigned int)(acc2[ip][2]));
        lo4.w = __uint_as_float((unsigned int)(acc2[ip][3]));
        hi4.x = __uint_as_float((unsigned int)(acc2[ip][0] >> 32));
        hi4.y = __uint_as_float((unsigned int)(acc2[ip][1] >> 32));
        hi4.z = __uint_as_float((unsigned int)(acc2[ip][2] >> 32));
        hi4.w = __uint_as_float((unsigned int)(acc2[ip][3] >> 32));
        int col = n_base + tx * 4;
        if (r0 < N)
            *(float4*)(g_support + (size_t)r0 * D_DIM + col) = lo4;
        if (r0 + 1 < N)
            *(float4*)(g_support + (size_t)(r0 + 1) * D_DIM + col) = hi4;
    }
}

// ---------------------------------------------------------------------------
// CSR build
// ---------------------------------------------------------------------------
__global__ void zero_cnt_kernel(int N)
{
    int i = blockIdx.x * blockDim.x + threadIdx.x;
    if (i < N) g_cnt[i] = 0;
}

__global__ void hist_kernel(const int* __restrict__ edst, int E)
{
    int e = blockIdx.x * blockDim.x + threadIdx.x;
    if (e < E) atomicAdd(&g_cnt[edst[e]], 1);
}

// pass 1: per-block totals of g_cnt chunks
__global__ __launch_bounds__(256) void scan1_kernel(int N)
{
    __shared__ int sT[256];
    int t = threadIdx.x;
    int base = blockIdx.x * SCAN_CHUNK + t * 8;
    int tot = 0;
    #pragma unroll
    for (int i = 0; i < 8; ++i) {
        int idx = base + i;
        tot += (idx < N) ? g_cnt[idx] : 0;
    }
    sT[t] = tot; __syncthreads();
    #pragma unroll
    for (int off = 128; off > 0; off >>= 1) {
        if (t < off) sT[t] += sT[t + off];
        __syncthreads();
    }
    if (t == 0) g_bsums[blockIdx.x] = sT[0];
}

// pass 2: serial exclusive scan of block sums (NB <= 64)
__global__ void scan2_kernel(int NB, int N)
{
    if (threadIdx.x == 0) {
        int acc = 0;
        for (int i = 0; i < NB; ++i) {
            int v = g_bsums[i];
            g_bsums[i] = acc;
            acc += v;
        }
        g_start[N] = acc;   // == E
    }
}

// pass 3: full exclusive scan -> g_start; reset g_cnt to 0 (cursor reuse)
__global__ __launch_bounds__(256) void scan3_kernel(int N)
{
    __shared__ int sT[256];
    int t = threadIdx.x;
    int base = blockIdx.x * SCAN_CHUNK + t * 8;

    int c[8];
    int tot = 0;
    #pragma unroll
    for (int i = 0; i < 8; ++i) {
        int idx = base + i;
        c[i] = (idx < N) ? g_cnt[idx] : 0;
        tot += c[i];
    }
    sT[t] = tot; __syncthreads();
    // inclusive Hillis-Steele
    #pragma unroll
    for (int off = 1; off < 256; off <<= 1) {
        int v = (t >= off) ? sT[t - off] : 0;
        __syncthreads();
        sT[t] += v;
        __syncthreads();
    }
    int run = g_bsums[blockIdx.x] + sT[t] - tot;   // exclusive thread base
    #pragma unroll
    for (int i = 0; i < 8; ++i) {
        int idx = base + i;
        if (idx < N) {
            g_start[idx] = run;
            g_cnt[idx]   = 0;
        }
        run += c[i];
    }
}

// reorder edges into dst-grouped packed (src, weight-bits)
__global__ void reorder_kernel(const int* __restrict__ esrc,
                               const int* __restrict__ edst,
                               const float* __restrict__ ew, int E)
{
    int e = blockIdx.x * blockDim.x + threadIdx.x;
    if (e < E) {
        int d = edst[e];
        int p = g_start[d] + atomicAdd(&g_cnt[d], 1);
        g_edges[p] = make_int2(esrc[e], __float_as_int(ew[e]));
    }
}

// ---------------------------------------------------------------------------
// Pull-gather: one warp per dst node. lane l covers floats [4l, 4l+4).
// acc starts at bias; single float4 store per lane. No atomics.
// 4x edge unroll (MLP vs ~234cy L2). 128-thread blocks: small retirement
// granularity hides per-node degree imbalance (max-of-k Poisson(16)).
// ---------------------------------------------------------------------------
__global__ __launch_bounds__(128) void gather_kernel(
    const float* __restrict__ bias, float* __restrict__ out, int N)
{
    int n    = (blockIdx.x * blockDim.x + threadIdx.x) >> 5;
    int lane = threadIdx.x & 31;
    if (n >= N) return;

    int j   = g_start[n];
    int end = g_start[n + 1];

    float4 a0 = __ldg((const float4*)(bias + lane * 4));
    float4 a1 = make_float4(0.f, 0.f, 0.f, 0.f);
    float4 a2 = make_float4(0.f, 0.f, 0.f, 0.f);
    float4 a3 = make_float4(0.f, 0.f, 0.f, 0.f);

    const size_t loff = (size_t)lane * 4;

    for (; j + 4 <= end; j += 4) {
        int2 e0 = __ldg(&g_edges[j]);
        int2 e1 = __ldg(&g_edges[j + 1]);
        int2 e2 = __ldg(&g_edges[j + 2]);
        int2 e3 = __ldg(&g_edges[j + 3]);
        float4 v0 = __ldg((const float4*)(g_support + (size_t)e0.x * D_DIM + loff));
        float4 v1 = __ldg((const float4*)(g_support + (size_t)e1.x * D_DIM + loff));
        float4 v2 = __ldg((const float4*)(g_support + (size_t)e2.x * D_DIM + loff));
        float4 v3 = __ldg((const float4*)(g_support + (size_t)e3.x * D_DIM + loff));
        float w0 = __int_as_float(e0.y), w1 = __int_as_float(e1.y);
        float w2 = __int_as_float(e2.y), w3 = __int_as_float(e3.y);
        a0.x += w0 * v0.x; a0.y += w0 * v0.y; a0.z += w0 * v0.z; a0.w += w0 * v0.w;
        a1.x += w1 * v1.x; a1.y += w1 * v1.y; a1.z += w1 * v1.z; a1.w += w1 * v1.w;
        a2.x += w2 * v2.x; a2.y += w2 * v2.y; a2.z += w2 * v2.z; a2.w += w2 * v2.w;
        a3.x += w3 * v3.x; a3.y += w3 * v3.y; a3.z += w3 * v3.z; a3.w += w3 * v3.w;
    }
    if (j + 2 <= end) {
        int2 e0 = __ldg(&g_edges[j]);
        int2 e1 = __ldg(&g_edges[j + 1]);
        float4 v0 = __ldg((const float4*)(g_support + (size_t)e0.x * D_DIM + loff));
        float4 v1 = __ldg((const float4*)(g_support + (size_t)e1.x * D_DIM + loff));
        float w0 = __int_as_float(e0.y), w1 = __int_as_float(e1.y);
        a0.x += w0 * v0.x; a0.y += w0 * v0.y; a0.z += w0 * v0.z; a0.w += w0 * v0.w;
        a1.x += w1 * v1.x; a1.y += w1 * v1.y; a1.z += w1 * v1.z; a1.w += w1 * v1.w;
        j += 2;
    }
    if (j < end) {
        int2 e0 = __ldg(&g_edges[j]);
        float4 v0 = __ldg((const float4*)(g_support + (size_t)e0.x * D_DIM + loff));
        float w0 = __int_as_float(e0.y);
        a0.x += w0 * v0.x; a0.y += w0 * v0.y; a0.z += w0 * v0.z; a0.w += w0 * v0.w;
    }

    a0.x += a1.x + a2.x + a3.x;
    a0.y += a1.y + a2.y + a3.y;
    a0.z += a1.z + a2.z + a3.z;
    a0.w += a1.w + a2.w + a3.w;

    *(float4*)(out + (size_t)n * D_DIM + loff) = a0;
}

// ---------------------------------------------------------------------------
extern "C" void kernel_launch(void* const* d_in, const int* in_sizes, int n_in,
                              void* d_out, int out_size)
{
    const float* x    = (const float*)d_in[0];
    const int*   esrc = (const int*)  d_in[1];
    const int*   edst = (const int*)  d_in[2];
    const float* ew   = (const float*)d_in[3];
    const float* W    = (const float*)d_in[4];
    const float* bias = (const float*)d_in[5];
    float*       out  = (float*)d_out;

    const int N = in_sizes[0] / D_DIM;   // 100000
    const int E = in_sizes[1];           // 1600000
    const int NB = (N + SCAN_CHUNK - 1) / SCAN_CHUNK;   // 49

    // Phase 1: support = x @ W
    dim3 ggrid((N + BM - 1) / BM, D_DIM / BN);
    gemm_kernel<<<ggrid, 256>>>(x, W, N);

    // Phase 2: CSR build by dst
    zero_cnt_kernel<<<(N + 255) / 256, 256>>>(N);
    hist_kernel<<<(E + 255) / 256, 256>>>(edst, E);
    scan1_kernel<<<NB, 256>>>(N);
    scan2_kernel<<<1, 32>>>(NB, N);
    scan3_kernel<<<NB, 256>>>(N);
    reorder_kernel<<<(E + 255) / 256, 256>>>(esrc, edst, ew, E);

    // Phase 3: pull-gather with bias (4 warps/block)
    int nblocks = (N * 32 + 127) / 128;
    gather_kernel<<<nblocks, 128>>>(bias, out, N);
}